// round 12
// baseline (speedup 1.0000x reference)
#include <cuda_runtime.h>
#include <cuda_fp16.h>
#include <cstdint>

#define Nn 8192
#define GAT_ALPHA 0.2f
#define LOG2E 1.4426950408889634f
#define NJQ 16
#define JW 512
#define NCH 8

// ---------------- scratch ----------------
__device__ float g_h[Nn * 64];
__device__ float g_ssrc[Nn];
__device__ float g_sdst[Nn];
__device__ unsigned g_gmax_u;
__device__ float g_eA[Nn];                 // A' = 2^(L*((ssrc+gmax) - m)) <= 1
__device__ float g_eC[Nn];                 // C' = 2^(L*(0.2*(ssrc+gmax) - m)) <= 1
__device__ uint2 g_eBDh[Nn / 2];           // packed half2 {B'(2k),B'(2k+1)},{D'...}
__device__ uint2 g_hBh[128 * 1024];        // fp16 B frags: [chunk64][ks4][nt8][lane32]
__device__ unsigned g_adjb[Nn * (Nn / 32)];
__device__ float g_o16[NJQ * Nn * 64];
__device__ float g_z16[NJQ * Nn];

// ---------------- helpers ----------------
__device__ __forceinline__ uint32_t h2pack(float hi, float lo) {
    uint32_t r;
    asm("cvt.rn.f16x2.f32 %0, %1, %2;" : "=r"(r) : "f"(hi), "f"(lo));
    return r;
}
__device__ __forceinline__ float2 h2unpack(uint32_t v) {
    __half2 h = *reinterpret_cast<__half2*>(&v);
    return __half22float2(h);
}
__device__ __forceinline__ uint32_t hmul2(uint32_t a, uint32_t b) {
    uint32_t d;
    asm("mul.f16x2 %0, %1, %2;" : "=r"(d) : "r"(a), "r"(b));
    return d;
}
__device__ __forceinline__ uint32_t hmax2(uint32_t a, uint32_t b) {
    uint32_t d;
    asm("max.f16x2 %0, %1, %2;" : "=r"(d) : "r"(a), "r"(b));
    return d;
}
__device__ __forceinline__ uint32_t hadd2(uint32_t a, uint32_t b) {
    uint32_t d;
    asm("add.f16x2 %0, %1, %2;" : "=r"(d) : "r"(a), "r"(b));
    return d;
}
__device__ __forceinline__ void mma_f16(float* c, uint32_t a0, uint32_t a1,
                                        uint32_t a2, uint32_t a3,
                                        uint32_t b0, uint32_t b1) {
    asm volatile(
        "mma.sync.aligned.m16n8k16.row.col.f32.f16.f16.f32 "
        "{%0,%1,%2,%3}, {%4,%5,%6,%7}, {%8,%9}, {%0,%1,%2,%3};"
        : "+f"(c[0]), "+f"(c[1]), "+f"(c[2]), "+f"(c[3])
        : "r"(a0), "r"(a1), "r"(a2), "r"(a3), "r"(b0), "r"(b1));
}
__device__ __forceinline__ uint32_t smem_u32(const void* p) {
    uint32_t a;
    asm("{ .reg .u64 t; cvta.to.shared.u64 t, %1; cvt.u32.u64 %0, t; }"
        : "=r"(a) : "l"(p));
    return a;
}
__device__ __forceinline__ void cp_async16(uint32_t s, const void* g) {
    asm volatile("{\n\t.reg .u64 ga;\n\tcvta.to.global.u64 ga, %1;\n\t"
                 "cp.async.cg.shared.global [%0], [ga], 16;\n\t}"
                 :: "r"(s), "l"(g) : "memory");
}
#define CP_COMMIT() asm volatile("cp.async.commit_group;" ::: "memory")
#define CP_WAIT1()  asm volatile("cp.async.wait_group 1;" ::: "memory")

__device__ __forceinline__ unsigned fenc(float f) {
    unsigned b = __float_as_uint(f);
    return (b & 0x80000000u) ? ~b : (b | 0x80000000u);
}
__device__ __forceinline__ float fdec(unsigned u) {
    unsigned b = (u & 0x80000000u) ? (u & 0x7FFFFFFFu) : ~u;
    return __uint_as_float(b);
}

// ---------------- kernel 1: fused [proj | pack] via block specialization ----------------
__global__ __launch_bounds__(256) void k_packproj(const float* __restrict__ input,
                                                  const float* __restrict__ Wm,
                                                  const int* __restrict__ adj) {
    __shared__ float in_s[16 * 512];
    const int t = threadIdx.x;
    if (blockIdx.x < 512) {
        const int i0 = blockIdx.x * 16;
#pragma unroll
        for (int q = 0; q < 8; ++q) {
            int idx = q * 256 + t;
            int row = idx >> 7, c4 = idx & 127;
            *(float4*)(in_s + row * 512 + c4 * 4) =
                *(const float4*)(input + (size_t)(i0 + row) * 512 + c4 * 4);
        }
        __syncthreads();
        const int f = t & 63, rg = t >> 6;
        float acc[4] = {0.f, 0.f, 0.f, 0.f};
        const float* ip = in_s + rg * 4 * 512;
        for (int k = 0; k < 512; k += 4) {
            float w0 = __ldg(Wm + (k + 0) * 64 + f);
            float w1 = __ldg(Wm + (k + 1) * 64 + f);
            float w2 = __ldg(Wm + (k + 2) * 64 + f);
            float w3 = __ldg(Wm + (k + 3) * 64 + f);
#pragma unroll
            for (int i = 0; i < 4; ++i) {
                float4 iv = *(const float4*)(ip + i * 512 + k);
                acc[i] = fmaf(iv.x, w0, acc[i]);
                acc[i] = fmaf(iv.y, w1, acc[i]);
                acc[i] = fmaf(iv.z, w2, acc[i]);
                acc[i] = fmaf(iv.w, w3, acc[i]);
            }
        }
#pragma unroll
        for (int i = 0; i < 4; ++i)
            g_h[(size_t)(i0 + rg * 4 + i) * 64 + f] = acc[i];
    } else {
        if (blockIdx.x == 512 && t == 0) g_gmax_u = 0u;
        const int l = t & 31;
        const size_t tid4 = (size_t)(blockIdx.x - 512) * 256 + t;
        const int4* adj4 = (const int4*)adj;
        int4 v[2][4];
#pragma unroll
        for (int k = 0; k < 4; ++k)
            v[0][k] = adj4[tid4 + (size_t)k * 524288];
#pragma unroll 1
        for (int it = 0; it < 32; it += 4) {        // depth-2 pipeline, batch 4
            const int cur = (it >> 2) & 1;
            if (it + 4 < 32) {
#pragma unroll
                for (int k = 0; k < 4; ++k)
                    v[cur ^ 1][k] = adj4[tid4 + (size_t)(it + 4 + k) * 524288];
            }
#pragma unroll
            for (int k = 0; k < 4; ++k) {
                int4 w4 = v[cur][k];
                unsigned n = (unsigned)(w4.x > 0) | ((unsigned)(w4.y > 0) << 1) |
                             ((unsigned)(w4.z > 0) << 2) | ((unsigned)(w4.w > 0) << 3);
                unsigned u = n << ((l & 7) * 4);
                u |= __shfl_xor_sync(0xffffffffu, u, 1);
                u |= __shfl_xor_sync(0xffffffffu, u, 2);
                u |= __shfl_xor_sync(0xffffffffu, u, 4);
                if ((l & 7) == 0)
                    g_adjb[(tid4 + (size_t)(it + k) * 524288) >> 3] = u;
            }
        }
    }
}

// ---------------- kernel 2: scores + fused global max ----------------
__global__ __launch_bounds__(256) void k_scores(const float* __restrict__ av) {
    __shared__ float sdm[8];
    const int t = threadIdx.x, w = t >> 5, l = t & 31;
    const int row = blockIdx.x * 8 + w;
    float v0 = g_h[(size_t)row * 64 + l];
    float v1 = g_h[(size_t)row * 64 + 32 + l];
    float ss = v0 * __ldg(av + l) + v1 * __ldg(av + 32 + l);
    float sd = v0 * __ldg(av + 64 + l) + v1 * __ldg(av + 96 + l);
#pragma unroll
    for (int o = 16; o; o >>= 1) {
        ss += __shfl_xor_sync(0xffffffffu, ss, o);
        sd += __shfl_xor_sync(0xffffffffu, sd, o);
    }
    if (l == 0) { g_ssrc[row] = ss; g_sdst[row] = sd; sdm[w] = sd; }
    __syncthreads();
    if (t == 0) {
        float m = sdm[0];
#pragma unroll
        for (int i = 1; i < 8; ++i) m = fmaxf(m, sdm[i]);
        atomicMax(&g_gmax_u, fenc(m));
    }
}

// ---------------- kernel 3: fp16 B frags + rebalanced separable-exp factors ----------------
__global__ __launch_bounds__(256) void k_prep() {
    __shared__ float hs[64 * 72];
    __shared__ float bsm[64], dsm[64];
    const int t = threadIdx.x;
    const int j0 = blockIdx.x * 64;
    const float gmax = fdec(g_gmax_u);
#pragma unroll
    for (int q = 0; q < 4; ++q) {
        int idx = q * 256 + t;
        int j = idx >> 4, f4 = idx & 15;
        float4 v = *(const float4*)(g_h + (size_t)(j0 + j) * 64 + f4 * 4);
        *(float4*)(hs + j * 72 + f4 * 4) = v;
    }
    if (t < 64) {
        int j = j0 + t;
        float sd = g_sdst[j];
        bsm[t] = exp2f(LOG2E * (sd - gmax));          // B' <= 1
        dsm[t] = exp2f(0.2f * LOG2E * (sd - gmax));   // D' <= 1
        float u = g_ssrc[j] + gmax;
        float m = fmaxf(u, GAT_ALPHA * u);
        g_eA[j] = exp2f(LOG2E * (u - m));             // A' <= 1
        g_eC[j] = exp2f(LOG2E * (0.2f * u - m));      // C' <= 1
    }
    __syncthreads();
    if (t < 32) {
        uint2 e;
        e.x = h2pack(bsm[2 * t + 1], bsm[2 * t]);
        e.y = h2pack(dsm[2 * t + 1], dsm[2 * t]);
        g_eBDh[j0 / 2 + t] = e;
    }
#pragma unroll
    for (int q = 0; q < 4; ++q) {
        int idx = q * 256 + t;                 // [ks4][nt8][lane32]
        int ks = idx >> 8, nt = (idx >> 5) & 7, lane = idx & 31;
        int g = lane >> 2, tig = lane & 3;
        int f = nt * 8 + g, jl = ks * 16 + 2 * tig;
        uint2 b;
        b.x = h2pack(hs[(jl + 1) * 72 + f], hs[jl * 72 + f]);
        b.y = h2pack(hs[(jl + 9) * 72 + f], hs[(jl + 8) * 72 + f]);
        g_hBh[(size_t)blockIdx.x * 1024 + idx] = b;
    }
}

// ---------------- kernel 4: fused register-P fp16 mma attention ----------------
// grid 512 = 32 i-tiles(M=256) x 16 j-splits(JW=512). 256 thr = 8 warps.
// Warp covers 32 rows {ra, ra+8, ra+16, ra+24}: each B fragment feeds 2 MMAs.
// P built in fp16x2 (HMUL2/HMAX2) + integer bitmask AND; z from exact MMA inputs.
#define SM_H   0         // fp16 B frags, 2 x 8KB double-buffered
#define SM_BD  16384     // packed eBD half2, 2 x 256B
#define SM_TOT 16896

__global__ __launch_bounds__(256, 2) void k_attn() {
    extern __shared__ char smem[];
    const uint32_t sb = smem_u32(smem);

    const int t = threadIdx.x;
    const int wid = t >> 5, lane = t & 31;
    const int g = lane >> 2, tig = lane & 3;
    const int i_tile = blockIdx.x >> 4, jq = blockIdx.x & 15;
    const int i0 = i_tile * 256, jb = jq * JW;

    const int ra = wid * 32 + g;
    uint32_t A2[4], C2[4];
    const unsigned* bw[4];
#pragma unroll
    for (int rr = 0; rr < 4; ++rr) {
        const int r = i0 + ra + rr * 8;
        float a = g_eA[r], c = g_eC[r];
        A2[rr] = h2pack(a, a);
        C2[rr] = h2pack(c, c);
        bw[rr] = g_adjb + (size_t)r * (Nn / 32) + (jb >> 5);
    }

    float acc[2][8][4];
#pragma unroll
    for (int s = 0; s < 2; ++s)
#pragma unroll
        for (int n = 0; n < 8; ++n)
#pragma unroll
            for (int k = 0; k < 4; ++k) acc[s][n][k] = 0.f;
    float zp[4] = {0.f, 0.f, 0.f, 0.f};

    auto stage = [&](int c, int buf) {
        const float4* src = (const float4*)g_hBh + (size_t)((jb + c * 64) >> 6) * 512;
        uint32_t dst = sb + SM_H + buf * 8192;
#pragma unroll
        for (int q = 0; q < 2; ++q)
            cp_async16(dst + (q * 256 + t) * 16, src + q * 256 + t);
        if (t < 16)
            cp_async16(sb + SM_BD + buf * 256 + t * 16,
                       (const char*)(g_eBDh + (jb + c * 64) / 2) + t * 16);
    };

    stage(0, 0); CP_COMMIT();
    stage(1, 1); CP_COMMIT();
    uint2 ab[4];
#pragma unroll
    for (int rr = 0; rr < 4; ++rr) ab[rr] = *(const uint2*)(bw[rr]);

    for (int c = 0; c < NCH; ++c) {
        const int buf = c & 1;
        CP_WAIT1();
        __syncthreads();

        const uint2* sBf = (const uint2*)(smem + SM_H + buf * 8192);
        const uint2* sBDh = (const uint2*)(smem + SM_BD + buf * 256);

        uint2 cb[4];
#pragma unroll
        for (int rr = 0; rr < 4; ++rr) cb[rr] = ab[rr];
        if (c + 1 < NCH) {
#pragma unroll
            for (int rr = 0; rr < 4; ++rr)
                ab[rr] = *(const uint2*)(bw[rr] + (c + 1) * 2);
        }

#pragma unroll
        for (int ks = 0; ks < 4; ++ks) {
            const int jl = ks * 16 + 2 * tig;
            const int s = jl & 31;
            uint2 bd0 = sBDh[ks * 8 + tig];       // {B2,D2} for j = jl, jl+1
            uint2 bd1 = sBDh[ks * 8 + tig + 4];   // {B2,D2} for j = jl+8, jl+9

            uint32_t afr[4][2];
#pragma unroll
            for (int rr = 0; rr < 4; ++rr) {
                const unsigned w = (ks < 2) ? cb[rr].x : cb[rr].y;
                const unsigned b = w >> s;
                const unsigned bh = b >> 8;
                unsigned mlo = (b & 1u) * 0xFFFFu + (b & 2u) * 0x7FFF8000u;
                unsigned mhi = (bh & 1u) * 0xFFFFu + (bh & 2u) * 0x7FFF8000u;
                uint32_t vlo = hmax2(hmul2(A2[rr], bd0.x), hmul2(C2[rr], bd0.y));
                uint32_t vhi = hmax2(hmul2(A2[rr], bd1.x), hmul2(C2[rr], bd1.y));
                uint32_t plo = vlo & mlo, phi = vhi & mhi;
                afr[rr][0] = plo;
                afr[rr][1] = phi;
                float2 zf = h2unpack(hadd2(plo, phi));
                zp[rr] += zf.x + zf.y;
            }

            const uint2* bb = sBf + ks * 256 + lane;
#pragma unroll
            for (int nt = 0; nt < 8; ++nt) {
                uint2 b = bb[nt * 32];
                mma_f16(acc[0][nt], afr[0][0], afr[1][0], afr[0][1], afr[1][1], b.x, b.y);
                mma_f16(acc[1][nt], afr[2][0], afr[3][0], afr[2][1], afr[3][1], b.x, b.y);
            }
        }
        __syncthreads();
        if (c + 2 < NCH) { stage(c + 2, buf); CP_COMMIT(); }
        else             { CP_COMMIT(); }
    }

    // ---- z quad-reduce + epilogue ----
#pragma unroll
    for (int rr = 0; rr < 4; ++rr) {
        zp[rr] += __shfl_xor_sync(0xffffffffu, zp[rr], 1);
        zp[rr] += __shfl_xor_sync(0xffffffffu, zp[rr], 2);
        if (tig == 0) g_z16[jq * Nn + i0 + ra + rr * 8] = zp[rr];
    }

    float* ob = g_o16 + (size_t)jq * Nn * 64;
#pragma unroll
    for (int s = 0; s < 2; ++s)
#pragma unroll
        for (int nt = 0; nt < 8; ++nt) {
            const int col = nt * 8 + tig * 2;
            *(float2*)(ob + (size_t)(i0 + ra + s * 16) * 64 + col) =
                make_float2(acc[s][nt][0], acc[s][nt][1]);
            *(float2*)(ob + (size_t)(i0 + ra + s * 16 + 8) * 64 + col) =
                make_float2(acc[s][nt][2], acc[s][nt][3]);
        }
}

// ---------------- kernel 5: combine + normalize ----------------
__global__ __launch_bounds__(256) void k_norm(float* __restrict__ out) {
    const int idx = blockIdx.x * 256 + threadIdx.x;
    const int row = idx >> 4;
    const float4* o0 = (const float4*)g_o16;
    float4 o = make_float4(0.f, 0.f, 0.f, 0.f);
    float z = 0.f;
#pragma unroll
    for (int k = 0; k < NJQ; ++k) {
        float4 a = o0[(size_t)k * Nn * 16 + idx];
        o.x += a.x; o.y += a.y; o.z += a.z; o.w += a.w;
        z += g_z16[k * Nn + row];
    }
    float zi = 1.0f / z;
    o.x *= zi; o.y *= zi; o.z *= zi; o.w *= zi;
    ((float4*)out)[idx] = o;
}

// ---------------- launch ----------------
extern "C" void kernel_launch(void* const* d_in, const int* in_sizes, int n_in,
                              void* d_out, int out_size) {
    const float* input = (const float*)d_in[0];
    const int*   adj   = (const int*)d_in[1];
    const float* Wm    = (const float*)d_in[2];
    const float* av    = (const float*)d_in[3];
    float* out = (float*)d_out;

    cudaFuncSetAttribute(k_attn, cudaFuncAttributeMaxDynamicSharedMemorySize, SM_TOT);

    k_packproj<<<2560, 256>>>(input, Wm, adj);
    k_scores<<<Nn / 8, 256>>>(av);
    k_prep<<<Nn / 64, 256>>>();
    k_attn<<<512, 256, SM_TOT>>>();
    k_norm<<<512, 256>>>(out);
}

// round 13
// speedup vs baseline: 1.2701x; 1.2701x over previous
#include <cuda_runtime.h>
#include <cuda_fp16.h>
#include <cstdint>

#define Nn 8192
#define GAT_ALPHA 0.2f
#define LOG2E 1.4426950408889634f
#define NJQ 16
#define JW 512
#define NCH 8

// ---------------- scratch ----------------
__device__ float g_h[Nn * 64];
__device__ float g_ssrc[Nn];
__device__ float g_sdst[Nn];
__device__ unsigned g_gmax_u;
__device__ float g_eA[Nn];                 // A' = 2^(L*((ssrc+gmax) - m)) <= 1
__device__ float g_eC[Nn];                 // C' = 2^(L*(0.2*(ssrc+gmax) - m)) <= 1
__device__ uint2 g_eBDh[Nn / 2];           // packed half2 {B'(2k),B'(2k+1)},{D'...}
__device__ uint2 g_hBh[128 * 1024];        // fp16 B frags: [chunk64][ks4][nt8][lane32]
__device__ unsigned g_adjb[Nn * (Nn / 32)];
__device__ float g_o16[NJQ * Nn * 64];
__device__ float g_z16[NJQ * Nn];

// ---------------- helpers ----------------
__device__ __forceinline__ uint32_t h2pack(float hi, float lo) {
    uint32_t r;
    asm("cvt.rn.f16x2.f32 %0, %1, %2;" : "=r"(r) : "f"(hi), "f"(lo));
    return r;
}
__device__ __forceinline__ float2 h2unpack(uint32_t v) {
    __half2 h = *reinterpret_cast<__half2*>(&v);
    return __half22float2(h);
}
__device__ __forceinline__ uint32_t hmul2(uint32_t a, uint32_t b) {
    uint32_t d;
    asm("mul.f16x2 %0, %1, %2;" : "=r"(d) : "r"(a), "r"(b));
    return d;
}
__device__ __forceinline__ uint32_t hmax2(uint32_t a, uint32_t b) {
    uint32_t d;
    asm("max.f16x2 %0, %1, %2;" : "=r"(d) : "r"(a), "r"(b));
    return d;
}
__device__ __forceinline__ uint32_t hadd2(uint32_t a, uint32_t b) {
    uint32_t d;
    asm("add.f16x2 %0, %1, %2;" : "=r"(d) : "r"(a), "r"(b));
    return d;
}
__device__ __forceinline__ void mma_f16(float* c, uint32_t a0, uint32_t a1,
                                        uint32_t a2, uint32_t a3,
                                        uint32_t b0, uint32_t b1) {
    asm volatile(
        "mma.sync.aligned.m16n8k16.row.col.f32.f16.f16.f32 "
        "{%0,%1,%2,%3}, {%4,%5,%6,%7}, {%8,%9}, {%0,%1,%2,%3};"
        : "+f"(c[0]), "+f"(c[1]), "+f"(c[2]), "+f"(c[3])
        : "r"(a0), "r"(a1), "r"(a2), "r"(a3), "r"(b0), "r"(b1));
}
__device__ __forceinline__ uint32_t smem_u32(const void* p) {
    uint32_t a;
    asm("{ .reg .u64 t; cvta.to.shared.u64 t, %1; cvt.u32.u64 %0, t; }"
        : "=r"(a) : "l"(p));
    return a;
}
__device__ __forceinline__ void cp_async16(uint32_t s, const void* g) {
    asm volatile("{\n\t.reg .u64 ga;\n\tcvta.to.global.u64 ga, %1;\n\t"
                 "cp.async.cg.shared.global [%0], [ga], 16;\n\t}"
                 :: "r"(s), "l"(g) : "memory");
}
#define CP_COMMIT() asm volatile("cp.async.commit_group;" ::: "memory")
#define CP_WAIT1()  asm volatile("cp.async.wait_group 1;" ::: "memory")

__device__ __forceinline__ unsigned fenc(float f) {
    unsigned b = __float_as_uint(f);
    return (b & 0x80000000u) ? ~b : (b | 0x80000000u);
}
__device__ __forceinline__ float fdec(unsigned u) {
    unsigned b = (u & 0x80000000u) ? (u & 0x7FFFFFFFu) : ~u;
    return __uint_as_float(b);
}

// ---------------- kernel 1: fused [proj | pack] via block specialization ----------------
// Pack branch: R10's exact MLP-4 loop (best measured: rest-of-pipeline 74.8us).
__global__ __launch_bounds__(256) void k_packproj(const float* __restrict__ input,
                                                  const float* __restrict__ Wm,
                                                  const int* __restrict__ adj) {
    __shared__ float in_s[16 * 512];
    const int t = threadIdx.x;
    if (blockIdx.x < 512) {
        const int i0 = blockIdx.x * 16;
#pragma unroll
        for (int q = 0; q < 8; ++q) {
            int idx = q * 256 + t;
            int row = idx >> 7, c4 = idx & 127;
            *(float4*)(in_s + row * 512 + c4 * 4) =
                *(const float4*)(input + (size_t)(i0 + row) * 512 + c4 * 4);
        }
        __syncthreads();
        const int f = t & 63, rg = t >> 6;
        float acc[4] = {0.f, 0.f, 0.f, 0.f};
        const float* ip = in_s + rg * 4 * 512;
        for (int k = 0; k < 512; k += 4) {
            float w0 = __ldg(Wm + (k + 0) * 64 + f);
            float w1 = __ldg(Wm + (k + 1) * 64 + f);
            float w2 = __ldg(Wm + (k + 2) * 64 + f);
            float w3 = __ldg(Wm + (k + 3) * 64 + f);
#pragma unroll
            for (int i = 0; i < 4; ++i) {
                float4 iv = *(const float4*)(ip + i * 512 + k);
                acc[i] = fmaf(iv.x, w0, acc[i]);
                acc[i] = fmaf(iv.y, w1, acc[i]);
                acc[i] = fmaf(iv.z, w2, acc[i]);
                acc[i] = fmaf(iv.w, w3, acc[i]);
            }
        }
#pragma unroll
        for (int i = 0; i < 4; ++i)
            g_h[(size_t)(i0 + rg * 4 + i) * 64 + f] = acc[i];
    } else {
        if (blockIdx.x == 512 && t == 0) g_gmax_u = 0u;
        const int l = t & 31;
        const size_t tid4 = (size_t)(blockIdx.x - 512) * 256 + t;
        const int4* adj4 = (const int4*)adj;
#pragma unroll 1
        for (int it = 0; it < 32; it += 4) {
            int4 v[4];
#pragma unroll
            for (int k = 0; k < 4; ++k)
                v[k] = adj4[tid4 + (size_t)(it + k) * 524288];
#pragma unroll
            for (int k = 0; k < 4; ++k) {
                unsigned n = (unsigned)(v[k].x > 0) | ((unsigned)(v[k].y > 0) << 1) |
                             ((unsigned)(v[k].z > 0) << 2) | ((unsigned)(v[k].w > 0) << 3);
                unsigned u = n << ((l & 7) * 4);
                u |= __shfl_xor_sync(0xffffffffu, u, 1);
                u |= __shfl_xor_sync(0xffffffffu, u, 2);
                u |= __shfl_xor_sync(0xffffffffu, u, 4);
                if ((l & 7) == 0)
                    g_adjb[(tid4 + (size_t)(it + k) * 524288) >> 3] = u;
            }
        }
    }
}

// ---------------- kernel 2: scores + fused global max ----------------
__global__ __launch_bounds__(256) void k_scores(const float* __restrict__ av) {
    __shared__ float sdm[8];
    const int t = threadIdx.x, w = t >> 5, l = t & 31;
    const int row = blockIdx.x * 8 + w;
    float v0 = g_h[(size_t)row * 64 + l];
    float v1 = g_h[(size_t)row * 64 + 32 + l];
    float ss = v0 * __ldg(av + l) + v1 * __ldg(av + 32 + l);
    float sd = v0 * __ldg(av + 64 + l) + v1 * __ldg(av + 96 + l);
#pragma unroll
    for (int o = 16; o; o >>= 1) {
        ss += __shfl_xor_sync(0xffffffffu, ss, o);
        sd += __shfl_xor_sync(0xffffffffu, sd, o);
    }
    if (l == 0) { g_ssrc[row] = ss; g_sdst[row] = sd; sdm[w] = sd; }
    __syncthreads();
    if (t == 0) {
        float m = sdm[0];
#pragma unroll
        for (int i = 1; i < 8; ++i) m = fmaxf(m, sdm[i]);
        atomicMax(&g_gmax_u, fenc(m));
    }
}

// ---------------- kernel 3: fp16 B frags + rebalanced separable-exp factors ----------------
__global__ __launch_bounds__(256) void k_prep() {
    __shared__ float hs[64 * 72];
    __shared__ float bsm[64], dsm[64];
    const int t = threadIdx.x;
    const int j0 = blockIdx.x * 64;
    const float gmax = fdec(g_gmax_u);
#pragma unroll
    for (int q = 0; q < 4; ++q) {
        int idx = q * 256 + t;
        int j = idx >> 4, f4 = idx & 15;
        float4 v = *(const float4*)(g_h + (size_t)(j0 + j) * 64 + f4 * 4);
        *(float4*)(hs + j * 72 + f4 * 4) = v;
    }
    if (t < 64) {
        int j = j0 + t;
        float sd = g_sdst[j];
        bsm[t] = exp2f(LOG2E * (sd - gmax));          // B' <= 1
        dsm[t] = exp2f(0.2f * LOG2E * (sd - gmax));   // D' <= 1
        float u = g_ssrc[j] + gmax;
        float m = fmaxf(u, GAT_ALPHA * u);
        g_eA[j] = exp2f(LOG2E * (u - m));             // A' <= 1
        g_eC[j] = exp2f(LOG2E * (0.2f * u - m));      // C' <= 1
    }
    __syncthreads();
    if (t < 32) {
        uint2 e;
        e.x = h2pack(bsm[2 * t + 1], bsm[2 * t]);
        e.y = h2pack(dsm[2 * t + 1], dsm[2 * t]);
        g_eBDh[j0 / 2 + t] = e;
    }
#pragma unroll
    for (int q = 0; q < 4; ++q) {
        int idx = q * 256 + t;                 // [ks4][nt8][lane32]
        int ks = idx >> 8, nt = (idx >> 5) & 7, lane = idx & 31;
        int g = lane >> 2, tig = lane & 3;
        int f = nt * 8 + g, jl = ks * 16 + 2 * tig;
        uint2 b;
        b.x = h2pack(hs[(jl + 1) * 72 + f], hs[jl * 72 + f]);
        b.y = h2pack(hs[(jl + 9) * 72 + f], hs[(jl + 8) * 72 + f]);
        g_hBh[(size_t)blockIdx.x * 1024 + idx] = b;
    }
}

// ---------------- kernel 4: fused register-P fp16 mma attention ----------------
// grid 512 = 32 i-tiles(M=256) x 16 j-splits(JW=512). 256 thr = 8 warps.
// Warp covers 32 rows; P in fp16x2 (HMUL2/HMAX2 + bitmask AND); z = exact MMA inputs.
#define SM_H   0         // fp16 B frags, 2 x 8KB double-buffered
#define SM_BD  16384     // packed eBD half2, 2 x 256B
#define SM_TOT 16896

__global__ __launch_bounds__(256, 2) void k_attn() {
    extern __shared__ char smem[];
    const uint32_t sb = smem_u32(smem);

    const int t = threadIdx.x;
    const int wid = t >> 5, lane = t & 31;
    const int g = lane >> 2, tig = lane & 3;
    const int i_tile = blockIdx.x >> 4, jq = blockIdx.x & 15;
    const int i0 = i_tile * 256, jb = jq * JW;

    const int ra = wid * 32 + g;
    uint32_t A2[4], C2[4];
    const unsigned* bw[4];
#pragma unroll
    for (int rr = 0; rr < 4; ++rr) {
        const int r = i0 + ra + rr * 8;
        float a = g_eA[r], c = g_eC[r];
        A2[rr] = h2pack(a, a);
        C2[rr] = h2pack(c, c);
        bw[rr] = g_adjb + (size_t)r * (Nn / 32) + (jb >> 5);
    }

    float acc[2][8][4];
#pragma unroll
    for (int s = 0; s < 2; ++s)
#pragma unroll
        for (int n = 0; n < 8; ++n)
#pragma unroll
            for (int k = 0; k < 4; ++k) acc[s][n][k] = 0.f;
    float zp[4] = {0.f, 0.f, 0.f, 0.f};

    auto stage = [&](int c, int buf) {
        const float4* src = (const float4*)g_hBh + (size_t)((jb + c * 64) >> 6) * 512;
        uint32_t dst = sb + SM_H + buf * 8192;
#pragma unroll
        for (int q = 0; q < 2; ++q)
            cp_async16(dst + (q * 256 + t) * 16, src + q * 256 + t);
        if (t < 16)
            cp_async16(sb + SM_BD + buf * 256 + t * 16,
                       (const char*)(g_eBDh + (jb + c * 64) / 2) + t * 16);
    };

    stage(0, 0); CP_COMMIT();
    stage(1, 1); CP_COMMIT();
    uint2 ab[4];
#pragma unroll
    for (int rr = 0; rr < 4; ++rr) ab[rr] = *(const uint2*)(bw[rr]);

    for (int c = 0; c < NCH; ++c) {
        const int buf = c & 1;
        CP_WAIT1();
        __syncthreads();

        const uint2* sBf = (const uint2*)(smem + SM_H + buf * 8192);
        const uint2* sBDh = (const uint2*)(smem + SM_BD + buf * 256);

        uint2 cb[4];
#pragma unroll
        for (int rr = 0; rr < 4; ++rr) cb[rr] = ab[rr];
        if (c + 1 < NCH) {
#pragma unroll
            for (int rr = 0; rr < 4; ++rr)
                ab[rr] = *(const uint2*)(bw[rr] + (c + 1) * 2);
        }

#pragma unroll
        for (int ks = 0; ks < 4; ++ks) {
            const int jl = ks * 16 + 2 * tig;
            const int s = jl & 31;
            uint2 bd0 = sBDh[ks * 8 + tig];       // {B2,D2} for j = jl, jl+1
            uint2 bd1 = sBDh[ks * 8 + tig + 4];   // {B2,D2} for j = jl+8, jl+9

            uint32_t afr[4][2];
#pragma unroll
            for (int rr = 0; rr < 4; ++rr) {
                const unsigned w = (ks < 2) ? cb[rr].x : cb[rr].y;
                const unsigned b = w >> s;
                const unsigned bh = b >> 8;
                unsigned mlo = (b & 1u) * 0xFFFFu + (b & 2u) * 0x7FFF8000u;
                unsigned mhi = (bh & 1u) * 0xFFFFu + (bh & 2u) * 0x7FFF8000u;
                uint32_t vlo = hmax2(hmul2(A2[rr], bd0.x), hmul2(C2[rr], bd0.y));
                uint32_t vhi = hmax2(hmul2(A2[rr], bd1.x), hmul2(C2[rr], bd1.y));
                uint32_t plo = vlo & mlo, phi = vhi & mhi;
                afr[rr][0] = plo;
                afr[rr][1] = phi;
                float2 zf = h2unpack(hadd2(plo, phi));
                zp[rr] += zf.x + zf.y;
            }

            const uint2* bb = sBf + ks * 256 + lane;
#pragma unroll
            for (int nt = 0; nt < 8; ++nt) {
                uint2 b = bb[nt * 32];
                mma_f16(acc[0][nt], afr[0][0], afr[1][0], afr[0][1], afr[1][1], b.x, b.y);
                mma_f16(acc[1][nt], afr[2][0], afr[3][0], afr[2][1], afr[3][1], b.x, b.y);
            }
        }
        __syncthreads();
        if (c + 2 < NCH) { stage(c + 2, buf); CP_COMMIT(); }
        else             { CP_COMMIT(); }
    }

    // ---- z quad-reduce + epilogue ----
#pragma unroll
    for (int rr = 0; rr < 4; ++rr) {
        zp[rr] += __shfl_xor_sync(0xffffffffu, zp[rr], 1);
        zp[rr] += __shfl_xor_sync(0xffffffffu, zp[rr], 2);
        if (tig == 0) g_z16[jq * Nn + i0 + ra + rr * 8] = zp[rr];
    }

    float* ob = g_o16 + (size_t)jq * Nn * 64;
#pragma unroll
    for (int s = 0; s < 2; ++s)
#pragma unroll
        for (int nt = 0; nt < 8; ++nt) {
            const int col = nt * 8 + tig * 2;
            *(float2*)(ob + (size_t)(i0 + ra + s * 16) * 64 + col) =
                make_float2(acc[s][nt][0], acc[s][nt][1]);
            *(float2*)(ob + (size_t)(i0 + ra + s * 16 + 8) * 64 + col) =
                make_float2(acc[s][nt][2], acc[s][nt][3]);
        }
}

// ---------------- kernel 5: combine + normalize ----------------
__global__ __launch_bounds__(256) void k_norm(float* __restrict__ out) {
    const int idx = blockIdx.x * 256 + threadIdx.x;
    const int row = idx >> 4;
    const float4* o0 = (const float4*)g_o16;
    float4 o = make_float4(0.f, 0.f, 0.f, 0.f);
    float z = 0.f;
#pragma unroll
    for (int k = 0; k < NJQ; ++k) {
        float4 a = o0[(size_t)k * Nn * 16 + idx];
        o.x += a.x; o.y += a.y; o.z += a.z; o.w += a.w;
        z += g_z16[k * Nn + row];
    }
    float zi = 1.0f / z;
    o.x *= zi; o.y *= zi; o.z *= zi; o.w *= zi;
    ((float4*)out)[idx] = o;
}

// ---------------- launch ----------------
extern "C" void kernel_launch(void* const* d_in, const int* in_sizes, int n_in,
                              void* d_out, int out_size) {
    const float* input = (const float*)d_in[0];
    const int*   adj   = (const int*)d_in[1];
    const float* Wm    = (const float*)d_in[2];
    const float* av    = (const float*)d_in[3];
    float* out = (float*)d_out;

    cudaFuncSetAttribute(k_attn, cudaFuncAttributeMaxDynamicSharedMemorySize, SM_TOT);

    k_packproj<<<2560, 256>>>(input, Wm, adj);
    k_scores<<<Nn / 8, 256>>>(av);
    k_prep<<<Nn / 64, 256>>>();
    k_attn<<<512, 256, SM_TOT>>>();
    k_norm<<<512, 256>>>(out);
}

// round 15
// speedup vs baseline: 1.2743x; 1.0033x over previous
#include <cuda_runtime.h>
#include <cuda_fp16.h>
#include <cstdint>

#define Nn 8192
#define GAT_ALPHA 0.2f
#define LOG2E 1.4426950408889634f
#define NJQ 16
#define JW 512
#define NCH 8
#define ONES2 0x3C003C00u   // half2 {1.0, 1.0}

// ---------------- scratch ----------------
__device__ float g_h[Nn * 64];
__device__ float g_ssrc[Nn];
__device__ float g_sdst[Nn];
__device__ unsigned g_gmax_u;
__device__ float g_eA[Nn];                 // A' = 2^(L*((ssrc+gmax) - m)) <= 1
__device__ float g_eC[Nn];                 // C' = 2^(L*(0.2*(ssrc+gmax) - m)) <= 1
__device__ uint2 g_eBDh[Nn / 2];           // packed half2 {B'(2k),B'(2k+1)},{D'...}
__device__ uint2 g_hBh[128 * 1024];        // fp16 B frags: [chunk64][ks4][nt8][lane32]
__device__ unsigned g_adjb[Nn * (Nn / 32)];
__device__ float g_o16[NJQ * Nn * 64];
__device__ float g_z16[NJQ * Nn];

// ---------------- helpers ----------------
__device__ __forceinline__ uint32_t h2pack(float hi, float lo) {
    uint32_t r;
    asm("cvt.rn.f16x2.f32 %0, %1, %2;" : "=r"(r) : "f"(hi), "f"(lo));
    return r;
}
__device__ __forceinline__ uint32_t hmul2(uint32_t a, uint32_t b) {
    uint32_t d;
    asm("mul.f16x2 %0, %1, %2;" : "=r"(d) : "r"(a), "r"(b));
    return d;
}
__device__ __forceinline__ uint32_t hmax2(uint32_t a, uint32_t b) {
    uint32_t d;
    asm("max.f16x2 %0, %1, %2;" : "=r"(d) : "r"(a), "r"(b));
    return d;
}
__device__ __forceinline__ void mma_f16(float* c, uint32_t a0, uint32_t a1,
                                        uint32_t a2, uint32_t a3,
                                        uint32_t b0, uint32_t b1) {
    asm volatile(
        "mma.sync.aligned.m16n8k16.row.col.f32.f16.f16.f32 "
        "{%0,%1,%2,%3}, {%4,%5,%6,%7}, {%8,%9}, {%0,%1,%2,%3};"
        : "+f"(c[0]), "+f"(c[1]), "+f"(c[2]), "+f"(c[3])
        : "r"(a0), "r"(a1), "r"(a2), "r"(a3), "r"(b0), "r"(b1));
}
__device__ __forceinline__ uint32_t smem_u32(const void* p) {
    uint32_t a;
    asm("{ .reg .u64 t; cvta.to.shared.u64 t, %1; cvt.u32.u64 %0, t; }"
        : "=r"(a) : "l"(p));
    return a;
}
__device__ __forceinline__ void cp_async16(uint32_t s, const void* g) {
    asm volatile("{\n\t.reg .u64 ga;\n\tcvta.to.global.u64 ga, %1;\n\t"
                 "cp.async.cg.shared.global [%0], [ga], 16;\n\t}"
                 :: "r"(s), "l"(g) : "memory");
}
#define CP_COMMIT() asm volatile("cp.async.commit_group;" ::: "memory")
#define CP_WAIT1()  asm volatile("cp.async.wait_group 1;" ::: "memory")

__device__ __forceinline__ unsigned fenc(float f) {
    unsigned b = __float_as_uint(f);
    return (b & 0x80000000u) ? ~b : (b | 0x80000000u);
}
__device__ __forceinline__ float fdec(unsigned u) {
    unsigned b = (u & 0x80000000u) ? (u & 0x7FFFFFFFu) : ~u;
    return __uint_as_float(b);
}

// ---------------- kernel 1: fused [proj | pack] via block specialization ----------------
__global__ __launch_bounds__(256) void k_packproj(const float* __restrict__ input,
                                                  const float* __restrict__ Wm,
                                                  const int* __restrict__ adj) {
    __shared__ float in_s[16 * 512];
    const int t = threadIdx.x;
    if (blockIdx.x < 512) {
        const int i0 = blockIdx.x * 16;
#pragma unroll
        for (int q = 0; q < 8; ++q) {
            int idx = q * 256 + t;
            int row = idx >> 7, c4 = idx & 127;
            *(float4*)(in_s + row * 512 + c4 * 4) =
                *(const float4*)(input + (size_t)(i0 + row) * 512 + c4 * 4);
        }
        __syncthreads();
        const int f = t & 63, rg = t >> 6;
        float acc[4] = {0.f, 0.f, 0.f, 0.f};
        const float* ip = in_s + rg * 4 * 512;
        for (int k = 0; k < 512; k += 4) {
            float w0 = __ldg(Wm + (k + 0) * 64 + f);
            float w1 = __ldg(Wm + (k + 1) * 64 + f);
            float w2 = __ldg(Wm + (k + 2) * 64 + f);
            float w3 = __ldg(Wm + (k + 3) * 64 + f);
#pragma unroll
            for (int i = 0; i < 4; ++i) {
                float4 iv = *(const float4*)(ip + i * 512 + k);
                acc[i] = fmaf(iv.x, w0, acc[i]);
                acc[i] = fmaf(iv.y, w1, acc[i]);
                acc[i] = fmaf(iv.z, w2, acc[i]);
                acc[i] = fmaf(iv.w, w3, acc[i]);
            }
        }
#pragma unroll
        for (int i = 0; i < 4; ++i)
            g_h[(size_t)(i0 + rg * 4 + i) * 64 + f] = acc[i];
    } else {
        if (blockIdx.x == 512 && t == 0) g_gmax_u = 0u;
        const int l = t & 31;
        const size_t tid4 = (size_t)(blockIdx.x - 512) * 256 + t;
        const int4* adj4 = (const int4*)adj;
#pragma unroll 1
        for (int it = 0; it < 32; it += 4) {
            int4 v[4];
#pragma unroll
            for (int k = 0; k < 4; ++k)
                v[k] = adj4[tid4 + (size_t)(it + k) * 524288];
#pragma unroll
            for (int k = 0; k < 4; ++k) {
                unsigned n = (unsigned)(v[k].x > 0) | ((unsigned)(v[k].y > 0) << 1) |
                             ((unsigned)(v[k].z > 0) << 2) | ((unsigned)(v[k].w > 0) << 3);
                unsigned u = n << ((l & 7) * 4);
                u |= __shfl_xor_sync(0xffffffffu, u, 1);
                u |= __shfl_xor_sync(0xffffffffu, u, 2);
                u |= __shfl_xor_sync(0xffffffffu, u, 4);
                if ((l & 7) == 0)
                    g_adjb[(tid4 + (size_t)(it + k) * 524288) >> 3] = u;
            }
        }
    }
}

// ---------------- kernel 2: scores + fused global max ----------------
__global__ __launch_bounds__(256) void k_scores(const float* __restrict__ av) {
    __shared__ float sdm[8];
    const int t = threadIdx.x, w = t >> 5, l = t & 31;
    const int row = blockIdx.x * 8 + w;
    float v0 = g_h[(size_t)row * 64 + l];
    float v1 = g_h[(size_t)row * 64 + 32 + l];
    float ss = v0 * __ldg(av + l) + v1 * __ldg(av + 32 + l);
    float sd = v0 * __ldg(av + 64 + l) + v1 * __ldg(av + 96 + l);
#pragma unroll
    for (int o = 16; o; o >>= 1) {
        ss += __shfl_xor_sync(0xffffffffu, ss, o);
        sd += __shfl_xor_sync(0xffffffffu, sd, o);
    }
    if (l == 0) { g_ssrc[row] = ss; g_sdst[row] = sd; sdm[w] = sd; }
    __syncthreads();
    if (t == 0) {
        float m = sdm[0];
#pragma unroll
        for (int i = 1; i < 8; ++i) m = fmaxf(m, sdm[i]);
        atomicMax(&g_gmax_u, fenc(m));
    }
}

// ---------------- kernel 3: fp16 B frags + rebalanced separable-exp factors ----------------
__global__ __launch_bounds__(256) void k_prep() {
    __shared__ float hs[64 * 72];
    __shared__ float bsm[64], dsm[64];
    const int t = threadIdx.x;
    const int j0 = blockIdx.x * 64;
    const float gmax = fdec(g_gmax_u);
#pragma unroll
    for (int q = 0; q < 4; ++q) {
        int idx = q * 256 + t;
        int j = idx >> 4, f4 = idx & 15;
        float4 v = *(const float4*)(g_h + (size_t)(j0 + j) * 64 + f4 * 4);
        *(float4*)(hs + j * 72 + f4 * 4) = v;
    }
    if (t < 64) {
        int j = j0 + t;
        float sd = g_sdst[j];
        bsm[t] = exp2f(LOG2E * (sd - gmax));          // B' <= 1
        dsm[t] = exp2f(0.2f * LOG2E * (sd - gmax));   // D' <= 1
        float u = g_ssrc[j] + gmax;
        float m = fmaxf(u, GAT_ALPHA * u);
        g_eA[j] = exp2f(LOG2E * (u - m));             // A' <= 1
        g_eC[j] = exp2f(LOG2E * (0.2f * u - m));      // C' <= 1
    }
    __syncthreads();
    if (t < 32) {
        uint2 e;
        e.x = h2pack(bsm[2 * t + 1], bsm[2 * t]);
        e.y = h2pack(dsm[2 * t + 1], dsm[2 * t]);
        g_eBDh[j0 / 2 + t] = e;
    }
#pragma unroll
    for (int q = 0; q < 4; ++q) {
        int idx = q * 256 + t;                 // [ks4][nt8][lane32]
        int ks = idx >> 8, nt = (idx >> 5) & 7, lane = idx & 31;
        int g = lane >> 2, tig = lane & 3;
        int f = nt * 8 + g, jl = ks * 16 + 2 * tig;
        uint2 b;
        b.x = h2pack(hs[(jl + 1) * 72 + f], hs[jl * 72 + f]);
        b.y = h2pack(hs[(jl + 9) * 72 + f], hs[(jl + 8) * 72 + f]);
        g_hBh[(size_t)blockIdx.x * 1024 + idx] = b;
    }
}

// ---------------- kernel 4: fused register-P fp16 mma attention ----------------
// grid 512 = 32 i-tiles(M=256) x 16 j-splits(JW=512). 256 thr = 8 warps.
// Warp covers 32 rows; P in fp16x2; z computed by ones-B MMA (tensor-core row sum).
#define SM_H   0         // fp16 B frags, 2 x 8KB double-buffered
#define SM_BD  16384     // packed eBD half2, 2 x 256B
#define SM_TOT 16896

__global__ __launch_bounds__(256, 2) void k_attn() {
    extern __shared__ char smem[];
    const uint32_t sb = smem_u32(smem);

    const int t = threadIdx.x;
    const int wid = t >> 5, lane = t & 31;
    const int g = lane >> 2, tig = lane & 3;
    const int i_tile = blockIdx.x >> 4, jq = blockIdx.x & 15;
    const int i0 = i_tile * 256, jb = jq * JW;

    const int ra = wid * 32 + g;
    uint32_t A2[4], C2[4];
    const unsigned* bw[4];
#pragma unroll
    for (int rr = 0; rr < 4; ++rr) {
        const int r = i0 + ra + rr * 8;
        float a = g_eA[r], c = g_eC[r];
        A2[rr] = h2pack(a, a);
        C2[rr] = h2pack(c, c);
        bw[rr] = g_adjb + (size_t)r * (Nn / 32) + (jb >> 5);
    }

    float acc[2][8][4];
#pragma unroll
    for (int s = 0; s < 2; ++s)
#pragma unroll
        for (int n = 0; n < 8; ++n)
#pragma unroll
            for (int k = 0; k < 4; ++k) acc[s][n][k] = 0.f;
    float accz[2][4];
#pragma unroll
    for (int s = 0; s < 2; ++s)
#pragma unroll
        for (int k = 0; k < 4; ++k) accz[s][k] = 0.f;

    auto stage = [&](int c, int buf) {
        const float4* src = (const float4*)g_hBh + (size_t)((jb + c * 64) >> 6) * 512;
        uint32_t dst = sb + SM_H + buf * 8192;
#pragma unroll
        for (int q = 0; q < 2; ++q)
            cp_async16(dst + (q * 256 + t) * 16, src + q * 256 + t);
        if (t < 16)
            cp_async16(sb + SM_BD + buf * 256 + t * 16,
                       (const char*)(g_eBDh + (jb + c * 64) / 2) + t * 16);
    };

    stage(0, 0); CP_COMMIT();
    stage(1, 1); CP_COMMIT();
    uint2 ab[4];
#pragma unroll
    for (int rr = 0; rr < 4; ++rr) ab[rr] = *(const uint2*)(bw[rr]);

    for (int c = 0; c < NCH; ++c) {
        const int buf = c & 1;
        CP_WAIT1();
        __syncthreads();

        const uint2* sBf = (const uint2*)(smem + SM_H + buf * 8192);
        const uint2* sBDh = (const uint2*)(smem + SM_BD + buf * 256);

        uint2 cb[4];
#pragma unroll
        for (int rr = 0; rr < 4; ++rr) cb[rr] = ab[rr];
        if (c + 1 < NCH) {
#pragma unroll
            for (int rr = 0; rr < 4; ++rr)
                ab[rr] = *(const uint2*)(bw[rr] + (c + 1) * 2);
        }

#pragma unroll
        for (int ks = 0; ks < 4; ++ks) {
            const int jl = ks * 16 + 2 * tig;
            const int s = jl & 31;
            uint2 bd0 = sBDh[ks * 8 + tig];       // {B2,D2} for j = jl, jl+1
            uint2 bd1 = sBDh[ks * 8 + tig + 4];   // {B2,D2} for j = jl+8, jl+9

            uint32_t afr[4][2];
#pragma unroll
            for (int rr = 0; rr < 4; ++rr) {
                const unsigned w = (ks < 2) ? cb[rr].x : cb[rr].y;
                const unsigned b = w >> s;
                const unsigned bh = b >> 8;
                unsigned mlo = (b & 1u) * 0xFFFFu + (b & 2u) * 0x7FFF8000u;
                unsigned mhi = (bh & 1u) * 0xFFFFu + (bh & 2u) * 0x7FFF8000u;
                uint32_t vlo = hmax2(hmul2(A2[rr], bd0.x), hmul2(C2[rr], bd0.y));
                uint32_t vhi = hmax2(hmul2(A2[rr], bd1.x), hmul2(C2[rr], bd1.y));
                afr[rr][0] = vlo & mlo;
                afr[rr][1] = vhi & mhi;
            }

            const uint2* bb = sBf + ks * 256 + lane;
#pragma unroll
            for (int nt = 0; nt < 8; ++nt) {
                uint2 b = bb[nt * 32];
                mma_f16(acc[0][nt], afr[0][0], afr[1][0], afr[0][1], afr[1][1], b.x, b.y);
                mma_f16(acc[1][nt], afr[2][0], afr[3][0], afr[2][1], afr[3][1], b.x, b.y);
            }
            // z row-sums on the tensor core (B = ones)
            mma_f16(accz[0], afr[0][0], afr[1][0], afr[0][1], afr[1][1], ONES2, ONES2);
            mma_f16(accz[1], afr[2][0], afr[3][0], afr[2][1], afr[3][1], ONES2, ONES2);
        }
        __syncthreads();
        if (c + 2 < NCH) { stage(c + 2, buf); CP_COMMIT(); }
        else             { CP_COMMIT(); }
    }

    // ---- epilogue: z duplicated across n-columns; lane tig==0 writes ----
    if (tig == 0) {
        float* zb = g_z16 + jq * Nn + i0;
        zb[ra]      = accz[0][0];
        zb[ra + 8]  = accz[0][2];
        zb[ra + 16] = accz[1][0];
        zb[ra + 24] = accz[1][2];
    }

    float* ob = g_o16 + (size_t)jq * Nn * 64;
#pragma unroll
    for (int s = 0; s < 2; ++s)
#pragma unroll
        for (int nt = 0; nt < 8; ++nt) {
            const int col = nt * 8 + tig * 2;
            *(float2*)(ob + (size_t)(i0 + ra + s * 16) * 64 + col) =
                make_float2(acc[s][nt][0], acc[s][nt][1]);
            *(float2*)(ob + (size_t)(i0 + ra + s * 16 + 8) * 64 + col) =
                make_float2(acc[s][nt][2], acc[s][nt][3]);
        }
}

// ---------------- kernel 5: combine + normalize ----------------
__global__ __launch_bounds__(256) void k_norm(float* __restrict__ out) {
    const int idx = blockIdx.x * 256 + threadIdx.x;
    const int row = idx >> 4;
    const float4* o0 = (const float4*)g_o16;
    float4 o = make_float4(0.f, 0.f, 0.f, 0.f);
    float z = 0.f;
#pragma unroll
    for (int k = 0; k < NJQ; ++k) {
        float4 a = o0[(size_t)k * Nn * 16 + idx];
        o.x += a.x; o.y += a.y; o.z += a.z; o.w += a.w;
        z += g_z16[k * Nn + row];
    }
    float zi = 1.0f / z;
    o.x *= zi; o.y *= zi; o.z *= zi; o.w *= zi;
    ((float4*)out)[idx] = o;
}

// ---------------- launch ----------------
extern "C" void kernel_launch(void* const* d_in, const int* in_sizes, int n_in,
                              void* d_out, int out_size) {
    const float* input = (const float*)d_in[0];
    const int*   adj   = (const int*)d_in[1];
    const float* Wm    = (const float*)d_in[2];
    const float* av    = (const float*)d_in[3];
    float* out = (float*)d_out;

    cudaFuncSetAttribute(k_attn, cudaFuncAttributeMaxDynamicSharedMemorySize, SM_TOT);

    k_packproj<<<2560, 256>>>(input, Wm, adj);
    k_scores<<<Nn / 8, 256>>>(av);
    k_prep<<<Nn / 64, 256>>>();
    k_attn<<<512, 256, SM_TOT>>>();
    k_norm<<<512, 256>>>(out);
}

// round 16
// speedup vs baseline: 1.3391x; 1.0509x over previous
#include <cuda_runtime.h>
#include <cuda_fp16.h>
#include <cstdint>

#define Nn 8192
#define GAT_ALPHA 0.2f
#define LOG2E 1.4426950408889634f
#define NJQ 8
#define JW 1024
#define NCH 16
#define ONES2 0x3C003C00u   // half2 {1.0, 1.0}

// ---------------- scratch ----------------
__device__ float g_h[Nn * 64];
__device__ float g_ssrc[Nn];
__device__ float g_sdst[Nn];
__device__ unsigned g_gmax_u;
__device__ float g_eA[Nn];                 // A' = 2^(L*((ssrc+gmax) - m)) <= 1
__device__ float g_eC[Nn];                 // C' = 2^(L*(0.2*(ssrc+gmax) - m)) <= 1
__device__ uint2 g_eBDh[Nn / 2];           // packed half2 {B'(2k),B'(2k+1)},{D'...}
__device__ uint2 g_hBh[128 * 1024];        // fp16 B frags: [chunk64][ks4][nt8][lane32]
__device__ unsigned g_adjb[Nn * (Nn / 32)];
__device__ float g_o8[NJQ * Nn * 64];
__device__ float g_z8[NJQ * Nn];

// ---------------- helpers ----------------
__device__ __forceinline__ uint32_t h2pack(float hi, float lo) {
    uint32_t r;
    asm("cvt.rn.f16x2.f32 %0, %1, %2;" : "=r"(r) : "f"(hi), "f"(lo));
    return r;
}
__device__ __forceinline__ uint32_t hmul2(uint32_t a, uint32_t b) {
    uint32_t d;
    asm("mul.f16x2 %0, %1, %2;" : "=r"(d) : "r"(a), "r"(b));
    return d;
}
__device__ __forceinline__ uint32_t hmax2(uint32_t a, uint32_t b) {
    uint32_t d;
    asm("max.f16x2 %0, %1, %2;" : "=r"(d) : "r"(a), "r"(b));
    return d;
}
__device__ __forceinline__ void mma_f16(float* c, uint32_t a0, uint32_t a1,
                                        uint32_t a2, uint32_t a3,
                                        uint32_t b0, uint32_t b1) {
    asm volatile(
        "mma.sync.aligned.m16n8k16.row.col.f32.f16.f16.f32 "
        "{%0,%1,%2,%3}, {%4,%5,%6,%7}, {%8,%9}, {%0,%1,%2,%3};"
        : "+f"(c[0]), "+f"(c[1]), "+f"(c[2]), "+f"(c[3])
        : "r"(a0), "r"(a1), "r"(a2), "r"(a3), "r"(b0), "r"(b1));
}
__device__ __forceinline__ uint32_t smem_u32(const void* p) {
    uint32_t a;
    asm("{ .reg .u64 t; cvta.to.shared.u64 t, %1; cvt.u32.u64 %0, t; }"
        : "=r"(a) : "l"(p));
    return a;
}
__device__ __forceinline__ void cp_async16(uint32_t s, const void* g) {
    asm volatile("{\n\t.reg .u64 ga;\n\tcvta.to.global.u64 ga, %1;\n\t"
                 "cp.async.cg.shared.global [%0], [ga], 16;\n\t}"
                 :: "r"(s), "l"(g) : "memory");
}
#define CP_COMMIT() asm volatile("cp.async.commit_group;" ::: "memory")
#define CP_WAIT1()  asm volatile("cp.async.wait_group 1;" ::: "memory")

__device__ __forceinline__ unsigned fenc(float f) {
    unsigned b = __float_as_uint(f);
    return (b & 0x80000000u) ? ~b : (b | 0x80000000u);
}
__device__ __forceinline__ float fdec(unsigned u) {
    unsigned b = (u & 0x80000000u) ? (u & 0x7FFFFFFFu) : ~u;
    return __uint_as_float(b);
}

// ---------------- kernel 1: fused [proj | pack] via block specialization ----------------
__global__ __launch_bounds__(256) void k_packproj(const float* __restrict__ input,
                                                  const float* __restrict__ Wm,
                                                  const int* __restrict__ adj) {
    __shared__ float in_s[16 * 512];
    const int t = threadIdx.x;
    if (blockIdx.x < 512) {
        const int i0 = blockIdx.x * 16;
#pragma unroll
        for (int q = 0; q < 8; ++q) {
            int idx = q * 256 + t;
            int row = idx >> 7, c4 = idx & 127;
            *(float4*)(in_s + row * 512 + c4 * 4) =
                *(const float4*)(input + (size_t)(i0 + row) * 512 + c4 * 4);
        }
        __syncthreads();
        const int f = t & 63, rg = t >> 6;
        float acc[4] = {0.f, 0.f, 0.f, 0.f};
        const float* ip = in_s + rg * 4 * 512;
        for (int k = 0; k < 512; k += 4) {
            float w0 = __ldg(Wm + (k + 0) * 64 + f);
            float w1 = __ldg(Wm + (k + 1) * 64 + f);
            float w2 = __ldg(Wm + (k + 2) * 64 + f);
            float w3 = __ldg(Wm + (k + 3) * 64 + f);
#pragma unroll
            for (int i = 0; i < 4; ++i) {
                float4 iv = *(const float4*)(ip + i * 512 + k);
                acc[i] = fmaf(iv.x, w0, acc[i]);
                acc[i] = fmaf(iv.y, w1, acc[i]);
                acc[i] = fmaf(iv.z, w2, acc[i]);
                acc[i] = fmaf(iv.w, w3, acc[i]);
            }
        }
#pragma unroll
        for (int i = 0; i < 4; ++i)
            g_h[(size_t)(i0 + rg * 4 + i) * 64 + f] = acc[i];
    } else {
        if (blockIdx.x == 512 && t == 0) g_gmax_u = 0u;
        const int l = t & 31;
        const size_t tid4 = (size_t)(blockIdx.x - 512) * 256 + t;
        const int4* adj4 = (const int4*)adj;
#pragma unroll 1
        for (int it = 0; it < 32; it += 4) {
            int4 v[4];
#pragma unroll
            for (int k = 0; k < 4; ++k)
                v[k] = adj4[tid4 + (size_t)(it + k) * 524288];
#pragma unroll
            for (int k = 0; k < 4; ++k) {
                unsigned n = (unsigned)(v[k].x > 0) | ((unsigned)(v[k].y > 0) << 1) |
                             ((unsigned)(v[k].z > 0) << 2) | ((unsigned)(v[k].w > 0) << 3);
                unsigned u = n << ((l & 7) * 4);
                u |= __shfl_xor_sync(0xffffffffu, u, 1);
                u |= __shfl_xor_sync(0xffffffffu, u, 2);
                u |= __shfl_xor_sync(0xffffffffu, u, 4);
                if ((l & 7) == 0)
                    g_adjb[(tid4 + (size_t)(it + k) * 524288) >> 3] = u;
            }
        }
    }
}

// ---------------- kernel 2: scores + fused global max ----------------
__global__ __launch_bounds__(256) void k_scores(const float* __restrict__ av) {
    __shared__ float sdm[8];
    const int t = threadIdx.x, w = t >> 5, l = t & 31;
    const int row = blockIdx.x * 8 + w;
    float v0 = g_h[(size_t)row * 64 + l];
    float v1 = g_h[(size_t)row * 64 + 32 + l];
    float ss = v0 * __ldg(av + l) + v1 * __ldg(av + 32 + l);
    float sd = v0 * __ldg(av + 64 + l) + v1 * __ldg(av + 96 + l);
#pragma unroll
    for (int o = 16; o; o >>= 1) {
        ss += __shfl_xor_sync(0xffffffffu, ss, o);
        sd += __shfl_xor_sync(0xffffffffu, sd, o);
    }
    if (l == 0) { g_ssrc[row] = ss; g_sdst[row] = sd; sdm[w] = sd; }
    __syncthreads();
    if (t == 0) {
        float m = sdm[0];
#pragma unroll
        for (int i = 1; i < 8; ++i) m = fmaxf(m, sdm[i]);
        atomicMax(&g_gmax_u, fenc(m));
    }
}

// ---------------- kernel 3: fp16 B frags + rebalanced separable-exp factors ----------------
__global__ __launch_bounds__(256) void k_prep() {
    __shared__ float hs[64 * 72];
    __shared__ float bsm[64], dsm[64];
    const int t = threadIdx.x;
    const int j0 = blockIdx.x * 64;
    const float gmax = fdec(g_gmax_u);
#pragma unroll
    for (int q = 0; q < 4; ++q) {
        int idx = q * 256 + t;
        int j = idx >> 4, f4 = idx & 15;
        float4 v = *(const float4*)(g_h + (size_t)(j0 + j) * 64 + f4 * 4);
        *(float4*)(hs + j * 72 + f4 * 4) = v;
    }
    if (t < 64) {
        int j = j0 + t;
        float sd = g_sdst[j];
        bsm[t] = exp2f(LOG2E * (sd - gmax));          // B' <= 1
        dsm[t] = exp2f(0.2f * LOG2E * (sd - gmax));   // D' <= 1
        float u = g_ssrc[j] + gmax;
        float m = fmaxf(u, GAT_ALPHA * u);
        g_eA[j] = exp2f(LOG2E * (u - m));             // A' <= 1
        g_eC[j] = exp2f(LOG2E * (0.2f * u - m));      // C' <= 1
    }
    __syncthreads();
    if (t < 32) {
        uint2 e;
        e.x = h2pack(bsm[2 * t + 1], bsm[2 * t]);
        e.y = h2pack(dsm[2 * t + 1], dsm[2 * t]);
        g_eBDh[j0 / 2 + t] = e;
    }
#pragma unroll
    for (int q = 0; q < 4; ++q) {
        int idx = q * 256 + t;                 // [ks4][nt8][lane32]
        int ks = idx >> 8, nt = (idx >> 5) & 7, lane = idx & 31;
        int g = lane >> 2, tig = lane & 3;
        int f = nt * 8 + g, jl = ks * 16 + 2 * tig;
        uint2 b;
        b.x = h2pack(hs[(jl + 1) * 72 + f], hs[jl * 72 + f]);
        b.y = h2pack(hs[(jl + 9) * 72 + f], hs[(jl + 8) * 72 + f]);
        g_hBh[(size_t)blockIdx.x * 1024 + idx] = b;
    }
}

// ---------------- kernel 4: fused register-P fp16 mma attention ----------------
// grid 256 = 32 i-tiles(M=256) x 8 j-splits(JW=1024) -> single wave (<=296 resident).
// 256 thr = 8 warps, warp covers 32 rows; z via ones-B MMA.
#define SM_H   0         // fp16 B frags, 2 x 8KB double-buffered
#define SM_BD  16384     // packed eBD half2, 2 x 256B
#define SM_TOT 16896

__global__ __launch_bounds__(256, 2) void k_attn() {
    extern __shared__ char smem[];
    const uint32_t sb = smem_u32(smem);

    const int t = threadIdx.x;
    const int wid = t >> 5, lane = t & 31;
    const int g = lane >> 2, tig = lane & 3;
    const int i_tile = blockIdx.x >> 3, jq = blockIdx.x & 7;
    const int i0 = i_tile * 256, jb = jq * JW;

    const int ra = wid * 32 + g;
    uint32_t A2[4], C2[4];
    const unsigned* bw[4];
#pragma unroll
    for (int rr = 0; rr < 4; ++rr) {
        const int r = i0 + ra + rr * 8;
        float a = g_eA[r], c = g_eC[r];
        A2[rr] = h2pack(a, a);
        C2[rr] = h2pack(c, c);
        bw[rr] = g_adjb + (size_t)r * (Nn / 32) + (jb >> 5);
    }

    float acc[2][8][4];
#pragma unroll
    for (int s = 0; s < 2; ++s)
#pragma unroll
        for (int n = 0; n < 8; ++n)
#pragma unroll
            for (int k = 0; k < 4; ++k) acc[s][n][k] = 0.f;
    float accz[2][4];
#pragma unroll
    for (int s = 0; s < 2; ++s)
#pragma unroll
        for (int k = 0; k < 4; ++k) accz[s][k] = 0.f;

    auto stage = [&](int c, int buf) {
        const float4* src = (const float4*)g_hBh + (size_t)((jb + c * 64) >> 6) * 512;
        uint32_t dst = sb + SM_H + buf * 8192;
#pragma unroll
        for (int q = 0; q < 2; ++q)
            cp_async16(dst + (q * 256 + t) * 16, src + q * 256 + t);
        if (t < 16)
            cp_async16(sb + SM_BD + buf * 256 + t * 16,
                       (const char*)(g_eBDh + (jb + c * 64) / 2) + t * 16);
    };

    stage(0, 0); CP_COMMIT();
    stage(1, 1); CP_COMMIT();
    uint2 ab[4];
#pragma unroll
    for (int rr = 0; rr < 4; ++rr) ab[rr] = *(const uint2*)(bw[rr]);

    for (int c = 0; c < NCH; ++c) {
        const int buf = c & 1;
        CP_WAIT1();
        __syncthreads();

        const uint2* sBf = (const uint2*)(smem + SM_H + buf * 8192);
        const uint2* sBDh = (const uint2*)(smem + SM_BD + buf * 256);

        uint2 cb[4];
#pragma unroll
        for (int rr = 0; rr < 4; ++rr) cb[rr] = ab[rr];
        if (c + 1 < NCH) {
#pragma unroll
            for (int rr = 0; rr < 4; ++rr)
                ab[rr] = *(const uint2*)(bw[rr] + (c + 1) * 2);
        }

#pragma unroll
        for (int ks = 0; ks < 4; ++ks) {
            const int jl = ks * 16 + 2 * tig;
            const int s = jl & 31;
            uint2 bd0 = sBDh[ks * 8 + tig];       // {B2,D2} for j = jl, jl+1
            uint2 bd1 = sBDh[ks * 8 + tig + 4];   // {B2,D2} for j = jl+8, jl+9

            uint32_t afr[4][2];
#pragma unroll
            for (int rr = 0; rr < 4; ++rr) {
                const unsigned w = (ks < 2) ? cb[rr].x : cb[rr].y;
                const unsigned b = w >> s;
                const unsigned bh = b >> 8;
                unsigned mlo = (b & 1u) * 0xFFFFu + (b & 2u) * 0x7FFF8000u;
                unsigned mhi = (bh & 1u) * 0xFFFFu + (bh & 2u) * 0x7FFF8000u;
                uint32_t vlo = hmax2(hmul2(A2[rr], bd0.x), hmul2(C2[rr], bd0.y));
                uint32_t vhi = hmax2(hmul2(A2[rr], bd1.x), hmul2(C2[rr], bd1.y));
                afr[rr][0] = vlo & mlo;
                afr[rr][1] = vhi & mhi;
            }

            const uint2* bb = sBf + ks * 256 + lane;
#pragma unroll
            for (int nt = 0; nt < 8; ++nt) {
                uint2 b = bb[nt * 32];
                mma_f16(acc[0][nt], afr[0][0], afr[1][0], afr[0][1], afr[1][1], b.x, b.y);
                mma_f16(acc[1][nt], afr[2][0], afr[3][0], afr[2][1], afr[3][1], b.x, b.y);
            }
            // z row-sums on the tensor core (B = ones)
            mma_f16(accz[0], afr[0][0], afr[1][0], afr[0][1], afr[1][1], ONES2, ONES2);
            mma_f16(accz[1], afr[2][0], afr[3][0], afr[2][1], afr[3][1], ONES2, ONES2);
        }
        __syncthreads();
        if (c + 2 < NCH) { stage(c + 2, buf); CP_COMMIT(); }
        else             { CP_COMMIT(); }
    }

    // ---- epilogue: z duplicated across n-columns; lane tig==0 writes ----
    if (tig == 0) {
        float* zb = g_z8 + jq * Nn + i0;
        zb[ra]      = accz[0][0];
        zb[ra + 8]  = accz[0][2];
        zb[ra + 16] = accz[1][0];
        zb[ra + 24] = accz[1][2];
    }

    float* ob = g_o8 + (size_t)jq * Nn * 64;
#pragma unroll
    for (int s = 0; s < 2; ++s)
#pragma unroll
        for (int nt = 0; nt < 8; ++nt) {
            const int col = nt * 8 + tig * 2;
            *(float2*)(ob + (size_t)(i0 + ra + s * 16) * 64 + col) =
                make_float2(acc[s][nt][0], acc[s][nt][1]);
            *(float2*)(ob + (size_t)(i0 + ra + s * 16 + 8) * 64 + col) =
                make_float2(acc[s][nt][2], acc[s][nt][3]);
        }
}

// ---------------- kernel 5: combine + normalize ----------------
__global__ __launch_bounds__(256) void k_norm(float* __restrict__ out) {
    const int idx = blockIdx.x * 256 + threadIdx.x;
    const int row = idx >> 4;
    const float4* o0 = (const float4*)g_o8;
    float4 o = make_float4(0.f, 0.f, 0.f, 0.f);
    float z = 0.f;
#pragma unroll
    for (int k = 0; k < NJQ; ++k) {
        float4 a = o0[(size_t)k * Nn * 16 + idx];
        o.x += a.x; o.y += a.y; o.z += a.z; o.w += a.w;
        z += g_z8[k * Nn + row];
    }
    float zi = 1.0f / z;
    o.x *= zi; o.y *= zi; o.z *= zi; o.w *= zi;
    ((float4*)out)[idx] = o;
}

// ---------------- launch ----------------
extern "C" void kernel_launch(void* const* d_in, const int* in_sizes, int n_in,
                              void* d_out, int out_size) {
    const float* input = (const float*)d_in[0];
    const int*   adj   = (const int*)d_in[1];
    const float* Wm    = (const float*)d_in[2];
    const float* av    = (const float*)d_in[3];
    float* out = (float*)d_out;

    cudaFuncSetAttribute(k_attn, cudaFuncAttributeMaxDynamicSharedMemorySize, SM_TOT);

    k_packproj<<<2560, 256>>>(input, Wm, adj);
    k_scores<<<Nn / 8, 256>>>(av);
    k_prep<<<Nn / 64, 256>>>();
    k_attn<<<256, 256, SM_TOT>>>();
    k_norm<<<512, 256>>>(out);
}